// round 5
// baseline (speedup 1.0000x reference)
#include <cuda_runtime.h>
#include <cuda_bf16.h>

// ---------------------------------------------------------------------------
// RotaryPosEmbedReal: multi-axis rotary tables gathered by analytically
// reconstructed position ids, scattered into (cap, ref, img, full) views.
//
// Compile-time shape constants (from reference_code):
//   B=8, ENC_LEN=512, D=128 (32+48+48)
//   ref images: 2 x (128x128 patches) = 32768 rows, img: 256x256 = 65536 rows
//   max_seq = 512 + 32768 + 65536 = 98816
//
// Store-bound scatter: ~1.62 GB stores, tables (~650 KB) stay L2-resident.
// ---------------------------------------------------------------------------

#define NSAMP   8
#define ENC     512
#define REFTOT  32768
#define IMGTOT  65536
#define MAXSEQ  98816   // 512 + 32768 + 65536
#define FEAT    128

// flattened-output element counts
#define SZ_CAP  (8LL * 512   * 128)   //    524288
#define SZ_REF  (8LL * 32768 * 128)   //  33554432
#define SZ_IMG  (8LL * 65536 * 128)   //  67108864
#define SZ_FRQ  (8LL * 98816 * 128)   // 101187584

// pytree flatten order: cap_cos, cap_sin, ref_cos, ref_sin, img_cos, img_sin,
//                       freqs_cos, freqs_sin, cap_lens(8), seq_lens(8)
#define OFF_CAPC  (0LL)
#define OFF_CAPS  (OFF_CAPC + SZ_CAP)
#define OFF_REFC  (OFF_CAPS + SZ_CAP)
#define OFF_REFS  (OFF_REFC + SZ_REF)
#define OFF_IMGC  (OFF_REFS + SZ_REF)
#define OFF_IMGS  (OFF_IMGC + SZ_IMG)
#define OFF_FRQC  (OFF_IMGS + SZ_IMG)
#define OFF_FRQS  (OFF_FRQC + SZ_FRQ)
#define OFF_TAIL  (OFF_FRQS + SZ_FRQ)          // 404750336
#define TOTAL_WITH_TAIL (OFF_TAIL + 16LL)      // 404750352

__device__ int g_cap[NSAMP];   // per-sample caption lengths (scratch)

// ---------------------------------------------------------------------------
// Kernel 0: sum attention mask rows -> g_cap; optionally write scalar tail.
// One block, 8 warps, warp w handles sample w (512 ints = 16 per lane).
// ---------------------------------------------------------------------------
__global__ void cap_kernel(const int* __restrict__ mask, float* __restrict__ out,
                           int write_tail) {
    int w    = threadIdx.x >> 5;   // sample
    int lane = threadIdx.x & 31;
    const int* row = mask + w * ENC;
    int s = 0;
    #pragma unroll
    for (int k = 0; k < ENC / 32; k++) s += row[lane + k * 32];
    #pragma unroll
    for (int off = 16; off > 0; off >>= 1) s += __shfl_xor_sync(0xFFFFFFFFu, s, off);
    if (lane == 0) {
        g_cap[w] = s;
        if (write_tail) {
            out[OFF_TAIL + w]     = (float)s;                     // cap_lens
            out[OFF_TAIL + 8 + w] = (float)(s + REFTOT + IMGTOT); // seq_lens
        }
    }
}

// ---------------------------------------------------------------------------
// Kernel 1: main gather/scatter. One thread per float4 of freqs.
// Block = 256 threads = 8 rows x 32 float4. grid = (98816/8, 8 samples).
// Stores are streaming (__stcs): output is write-once and 12x L2 capacity —
// keep L2 lines for the rotary tables every thread reads.
// Rows c..511 also zero-fill the padded caption slot (folded cappad kernel).
// ---------------------------------------------------------------------------
__global__ void __launch_bounds__(256)
main_kernel(const float* __restrict__ cos0, const float* __restrict__ sin0,
            const float* __restrict__ cos1, const float* __restrict__ sin1,
            const float* __restrict__ cos2, const float* __restrict__ sin2,
            float* __restrict__ out) {
    const int i   = blockIdx.y;
    const int row = blockIdx.x * 8 + (threadIdx.x >> 5);
    const int t   = threadIdx.x & 31;          // float4 index within row
    const int d   = t << 2;                    // feature offset 0..124
    const int c   = g_cap[i];

    int p0, p1, p2;
    long long sro = -1;        // split-region cos element offset (row base)
    long long sdelta = 0;      // cos->sin delta within that split

    if (row < c) {
        p0 = row; p1 = row; p2 = row;
        sro = OFF_CAPC + ((long long)i * ENC + row) * FEAT;
        sdelta = SZ_CAP;
    } else if (row < c + REFTOT) {
        int local = row - c;               // 0..32767
        int half  = local >> 14;           // which ref image (16384 rows each)
        int ll    = local & 16383;
        p0 = c + half * 128;               // pe_shift: c, then c+128
        p1 = ll >> 7;                      // row within 128x128 patch grid
        p2 = ll & 127;
        sro = OFF_REFC + ((long long)i * REFTOT + local) * FEAT;
        sdelta = SZ_REF;
    } else if (row < c + REFTOT + IMGTOT) {
        int local = row - c - REFTOT;      // 0..65535
        p0 = c + 256;                      // pe_shift after both refs
        p1 = local >> 8;                   // 256x256 patch grid
        p2 = local & 255;
        sro = OFF_IMGC + ((long long)i * IMGTOT + local) * FEAT;
        sdelta = SZ_IMG;
    } else {
        // padding rows of freqs: pos id 0 -> cos=1, sin=0 (table row 0)
        p0 = 0; p1 = 0; p2 = 0;
    }

    const float* ctab; const float* stab; int idx;
    if (d < 32)      { ctab = cos0; stab = sin0; idx = p0 * 32 + d;        }
    else if (d < 80) { ctab = cos1; stab = sin1; idx = p1 * 48 + (d - 32); }
    else             { ctab = cos2; stab = sin2; idx = p2 * 48 + (d - 80); }

    const float4 cv = __ldg(reinterpret_cast<const float4*>(ctab + idx));
    const float4 sv = __ldg(reinterpret_cast<const float4*>(stab + idx));

    const long long fro = OFF_FRQC + ((long long)i * MAXSEQ + row) * FEAT + d;
    __stcs(reinterpret_cast<float4*>(out + fro),          cv);
    __stcs(reinterpret_cast<float4*>(out + fro + SZ_FRQ), sv);

    if (sro >= 0) {
        __stcs(reinterpret_cast<float4*>(out + sro + d),          cv);
        __stcs(reinterpret_cast<float4*>(out + sro + d + sdelta), sv);
    }

    // caption padding rows: cap_cos/cap_sin[i, c..511] = 0
    if (row >= c && row < ENC) {
        const long long po = OFF_CAPC + ((long long)i * ENC + row) * FEAT + d;
        const float4 z = make_float4(0.f, 0.f, 0.f, 0.f);
        __stcs(reinterpret_cast<float4*>(out + po),          z);
        __stcs(reinterpret_cast<float4*>(out + po + SZ_CAP), z);
    }
}

extern "C" void kernel_launch(void* const* d_in, const int* in_sizes, int n_in,
                              void* d_out, int out_size) {
    const int*   mask = (const int*)  d_in[0];
    const float* cos0 = (const float*)d_in[1];
    const float* sin0 = (const float*)d_in[2];
    const float* cos1 = (const float*)d_in[3];
    const float* sin1 = (const float*)d_in[4];
    const float* cos2 = (const float*)d_in[5];
    const float* sin2 = (const float*)d_in[6];
    float* out = (float*)d_out;

    const int write_tail = ((long long)out_size == TOTAL_WITH_TAIL) ? 1 : 0;

    cap_kernel<<<1, 256>>>(mask, out, write_tail);

    dim3 g1(MAXSEQ / 8, NSAMP);
    main_kernel<<<g1, 256>>>(cos0, sin0, cos1, sin1, cos2, sin2, out);
}

// round 12
// speedup vs baseline: 1.0004x; 1.0004x over previous
#include <cuda_runtime.h>
#include <cuda_bf16.h>

// ---------------------------------------------------------------------------
// RotaryPosEmbedReal: multi-axis rotary tables gathered by analytically
// reconstructed position ids, scattered into (cap, ref, img, full) views.
//
// B=8, ENC_LEN=512, D=128 (32+48+48); 2 ref imgs 128x128 patches (32768 rows),
// target 256x256 (65536 rows); max_seq = 98816.
//
// Measured R5: 215.5us, DRAM 92.3%, 7318 GB/s (91.5% of spec) -> at roofline.
// Candidate (untested; broker timeouts R6-R11): PDL to hide cap_kernel +
// launch gap (~2.4us). Prediction: 212-214us.
// ---------------------------------------------------------------------------

#define NSAMP   8
#define ENC     512
#define REFTOT  32768
#define IMGTOT  65536
#define MAXSEQ  98816   // 512 + 32768 + 65536
#define FEAT    128

// flattened-output element counts
#define SZ_CAP  (8LL * 512   * 128)   //    524288
#define SZ_REF  (8LL * 32768 * 128)   //  33554432
#define SZ_IMG  (8LL * 65536 * 128)   //  67108864
#define SZ_FRQ  (8LL * 98816 * 128)   // 101187584

// pytree flatten order: cap_cos, cap_sin, ref_cos, ref_sin, img_cos, img_sin,
//                       freqs_cos, freqs_sin, cap_lens(8), seq_lens(8)
#define OFF_CAPC  (0LL)
#define OFF_CAPS  (OFF_CAPC + SZ_CAP)
#define OFF_REFC  (OFF_CAPS + SZ_CAP)
#define OFF_REFS  (OFF_REFC + SZ_REF)
#define OFF_IMGC  (OFF_REFS + SZ_REF)
#define OFF_IMGS  (OFF_IMGC + SZ_IMG)
#define OFF_FRQC  (OFF_IMGS + SZ_IMG)
#define OFF_FRQS  (OFF_FRQC + SZ_FRQ)
#define OFF_TAIL  (OFF_FRQS + SZ_FRQ)          // 404750336
#define TOTAL_WITH_TAIL (OFF_TAIL + 16LL)      // 404750352

__device__ int g_cap[NSAMP];   // per-sample caption lengths (scratch)

// ---------------------------------------------------------------------------
// Kernel 0: sum attention mask rows -> g_cap; optionally write scalar tail.
// One block, 8 warps, warp w handles sample w (512 ints = 16 per lane).
// Fires programmatic-launch trigger once g_cap is written (PDL primary).
// ---------------------------------------------------------------------------
__global__ void cap_kernel(const int* __restrict__ mask, float* __restrict__ out,
                           int write_tail) {
    int w    = threadIdx.x >> 5;   // sample
    int lane = threadIdx.x & 31;
    const int* row = mask + w * ENC;
    int s = 0;
    #pragma unroll
    for (int k = 0; k < ENC / 32; k++) s += row[lane + k * 32];
    #pragma unroll
    for (int off = 16; off > 0; off >>= 1) s += __shfl_xor_sync(0xFFFFFFFFu, s, off);
    if (lane == 0) {
        g_cap[w] = s;
        if (write_tail) {
            out[OFF_TAIL + w]     = (float)s;                     // cap_lens
            out[OFF_TAIL + 8 + w] = (float)(s + REFTOT + IMGTOT); // seq_lens
        }
    }
    // allow the dependent main_kernel to begin launching; its
    // cudaGridDependencySynchronize() makes the g_cap writes visible.
    cudaTriggerProgrammaticLaunchCompletion();
}

// ---------------------------------------------------------------------------
// Kernel 1: main gather/scatter. One thread per float4 of freqs.
// Block = 256 threads = 8 rows x 32 float4. grid = (98816/8, 8 samples).
// Streaming stores (__stcs): output is write-once, 12x L2 capacity.
// Rows c..511 also zero-fill the padded caption slot.
// ---------------------------------------------------------------------------
__global__ void __launch_bounds__(256)
main_kernel(const float* __restrict__ cos0, const float* __restrict__ sin0,
            const float* __restrict__ cos1, const float* __restrict__ sin1,
            const float* __restrict__ cos2, const float* __restrict__ sin2,
            float* __restrict__ out) {
    const int i   = blockIdx.y;
    const int row = blockIdx.x * 8 + (threadIdx.x >> 5);
    const int t   = threadIdx.x & 31;          // float4 index within row
    const int d   = t << 2;                    // feature offset 0..124

    // PDL: wait for cap_kernel's g_cap writes to be visible.
    cudaGridDependencySynchronize();
    const int c   = g_cap[i];

    int p0, p1, p2;
    long long sro = -1;        // split-region cos element offset (row base)
    long long sdelta = 0;      // cos->sin delta within that split

    if (row < c) {
        p0 = row; p1 = row; p2 = row;
        sro = OFF_CAPC + ((long long)i * ENC + row) * FEAT;
        sdelta = SZ_CAP;
    } else if (row < c + REFTOT) {
        int local = row - c;               // 0..32767
        int half  = local >> 14;           // which ref image (16384 rows each)
        int ll    = local & 16383;
        p0 = c + half * 128;               // pe_shift: c, then c+128
        p1 = ll >> 7;                      // row within 128x128 patch grid
        p2 = ll & 127;
        sro = OFF_REFC + ((long long)i * REFTOT + local) * FEAT;
        sdelta = SZ_REF;
    } else if (row < c + REFTOT + IMGTOT) {
        int local = row - c - REFTOT;      // 0..65535
        p0 = c + 256;                      // pe_shift after both refs
        p1 = local >> 8;                   // 256x256 patch grid
        p2 = local & 255;
        sro = OFF_IMGC + ((long long)i * IMGTOT + local) * FEAT;
        sdelta = SZ_IMG;
    } else {
        // padding rows of freqs: pos id 0 -> cos=1, sin=0 (table row 0)
        p0 = 0; p1 = 0; p2 = 0;
    }

    const float* ctab; const float* stab; int idx;
    if (d < 32)      { ctab = cos0; stab = sin0; idx = p0 * 32 + d;        }
    else if (d < 80) { ctab = cos1; stab = sin1; idx = p1 * 48 + (d - 32); }
    else             { ctab = cos2; stab = sin2; idx = p2 * 48 + (d - 80); }

    const float4 cv = __ldg(reinterpret_cast<const float4*>(ctab + idx));
    const float4 sv = __ldg(reinterpret_cast<const float4*>(stab + idx));

    const long long fro = OFF_FRQC + ((long long)i * MAXSEQ + row) * FEAT + d;
    __stcs(reinterpret_cast<float4*>(out + fro),          cv);
    __stcs(reinterpret_cast<float4*>(out + fro + SZ_FRQ), sv);

    if (sro >= 0) {
        __stcs(reinterpret_cast<float4*>(out + sro + d),          cv);
        __stcs(reinterpret_cast<float4*>(out + sro + d + sdelta), sv);
    }

    // caption padding rows: cap_cos/cap_sin[i, c..511] = 0
    if (row >= c && row < ENC) {
        const long long po = OFF_CAPC + ((long long)i * ENC + row) * FEAT + d;
        const float4 z = make_float4(0.f, 0.f, 0.f, 0.f);
        __stcs(reinterpret_cast<float4*>(out + po),          z);
        __stcs(reinterpret_cast<float4*>(out + po + SZ_CAP), z);
    }
}

extern "C" void kernel_launch(void* const* d_in, const int* in_sizes, int n_in,
                              void* d_out, int out_size) {
    const int*   mask = (const int*)  d_in[0];
    const float* cos0 = (const float*)d_in[1];
    const float* sin0 = (const float*)d_in[2];
    const float* cos1 = (const float*)d_in[3];
    const float* sin1 = (const float*)d_in[4];
    const float* cos2 = (const float*)d_in[5];
    const float* sin2 = (const float*)d_in[6];
    float* out = (float*)d_out;

    int write_tail = ((long long)out_size == TOTAL_WITH_TAIL) ? 1 : 0;

    // primary: plain launch
    cap_kernel<<<1, 256>>>(mask, out, write_tail);

    // secondary: programmatic dependent launch (overlaps launch with primary)
    cudaLaunchConfig_t cfg = {};
    cfg.gridDim  = dim3(MAXSEQ / 8, NSAMP, 1);
    cfg.blockDim = dim3(256, 1, 1);
    cudaLaunchAttribute attrs[1];
    attrs[0].id = cudaLaunchAttributeProgrammaticStreamSerialization;
    attrs[0].val.programmaticStreamSerializationAllowed = 1;
    cfg.attrs = attrs;
    cfg.numAttrs = 1;
    cudaLaunchKernelEx(&cfg, main_kernel, cos0, sin0, cos1, sin1, cos2, sin2, out);
}